// round 4
// baseline (speedup 1.0000x reference)
#include <cuda_runtime.h>
#include <cstdint>

// FPS on GB300, round 4.
// CS=16 clusters (128 CTAs), 512 thr/CTA, coords register-resident.
// Per-step cluster exchange: hub-and-spoke DSMEM flag protocol (NO
// barrier.cluster in the loop):
//   spoke: warp0 REDUX -> one lane st.shared::cluster candidate + release
//          flag(s+1) into CTA0 smem
//   hub  : warp0 polls local flags, REDUX over CS candidates, stores winner
//          xyz + release flag(s+1) into every CTA's smem
//   all  : poll local result flag (broadcast LDS), read winner xyz.
// Monotonic counters make double-buffering unnecessary: slot overwrite at
// step s+1 can only happen after the writer saw result(s), which the hub
// publishes only after reading slot(s); result overwrite at s+1 happens only
// after all CTAs' candidates(s+1), which follow each CTA's __syncthreads(s+1),
// which every thread passes only after reading result(s).

#define NPTS     131072
#define BATCH    8
#define NSAMP    4096
#define NT       512
#define BIGF     1e10f

#define ADD2(o, a, b) asm("add.rn.f32x2 %0, %1, %2;" : "=l"(o) : "l"(a), "l"(b))
#define MUL2(o, a, b) asm("mul.rn.f32x2 %0, %1, %2;" : "=l"(o) : "l"(a), "l"(b))
#define PACK2(o, lo, hi) asm("mov.b64 %0, {%1, %2};" : "=l"(o) : "f"(lo), "f"(hi))
#define UNPACK2(lo, hi, in) asm("mov.b64 {%0, %1}, %2;" : "=f"(lo), "=f"(hi) : "l"(in))

static __device__ __forceinline__ uint32_t smem_u32(const void* p) {
    uint32_t a;
    asm("{ .reg .u64 t; cvta.to.shared.u64 t, %1; cvt.u32.u64 %0, t; }"
        : "=r"(a) : "l"(p));
    return a;
}
static __device__ __forceinline__ uint32_t mapa_rank(uint32_t local, uint32_t rank) {
    uint32_t r;
    asm("mapa.shared::cluster.u32 %0, %1, %2;" : "=r"(r) : "r"(local), "r"(rank));
    return r;
}
static __device__ __forceinline__ void st_cluster_b64(uint32_t addr, unsigned long long v) {
    asm volatile("st.shared::cluster.b64 [%0], %1;" :: "r"(addr), "l"(v) : "memory");
}
static __device__ __forceinline__ void st_cluster_b32(uint32_t addr, uint32_t v) {
    asm volatile("st.shared::cluster.b32 [%0], %1;" :: "r"(addr), "r"(v) : "memory");
}
static __device__ __forceinline__ void st_rel_cluster_b32(uint32_t addr, uint32_t v) {
    asm volatile("st.release.cluster.shared::cluster.b32 [%0], %1;"
                 :: "r"(addr), "r"(v) : "memory");
}
static __device__ __forceinline__ unsigned ld_acq_cluster(uint32_t addr) {
    unsigned v;
    asm volatile("ld.acquire.cluster.shared::cta.b32 %0, [%1];"
                 : "=r"(v) : "r"(addr) : "memory");
    return v;
}
static __device__ __forceinline__ unsigned long long f2_to_u64(float a, float b) {
    unsigned long long r;
    asm("mov.b64 %0, {%1, %2};" : "=l"(r) : "f"(a), "f"(b));
    return r;
}
static __device__ __forceinline__ void cluster_barrier() {
    asm volatile("barrier.cluster.arrive.aligned;" ::: "memory");
    asm volatile("barrier.cluster.wait.aligned;" ::: "memory");
}

template <int CS, bool REGC>
__device__ __forceinline__ void fps_body(const float* __restrict__ pts,
                                         float* __restrict__ out)
{
    constexpr int PPC    = NPTS / CS;
    constexpr int QPT    = PPC / (4 * NT);
    constexpr int LOGPPC = (CS == 16) ? 13 : 14;

    extern __shared__ float sm[];
    float*    smx   = sm;
    float*    smy   = sm + PPC;
    float*    smz   = sm + 2 * PPC;
    unsigned* wv    = (unsigned*)(sm + 3 * PPC);   // [32] warp best value bits
    unsigned* wi    = wv + 32;                     // [32] warp best local idx
    float*    slots = (float*)(wi + 32);           // [CS][8] hub candidate slots
    unsigned* sflag = (unsigned*)(slots + CS * 8); // [CS] hub slot flags
    float*    res   = (float*)(sflag + CS);        // [3] winner xyz (+pad)
    unsigned* rflag = (unsigned*)(res + 3);        // [1] result flag

    const int tid  = threadIdx.x;
    const int lane = tid & 31;
    const int warp = tid >> 5;
    uint32_t rank;
    asm("mov.u32 %0, %%cluster_ctarank;" : "=r"(rank));
    const int b = blockIdx.x / CS;
    const float* P = pts + (size_t)b * NPTS * 3;
    const int base = (int)rank * PPC;

    // Load this CTA's coords: SMEM SoA copy (winner lookup) + packed f32x2
    // register cache when REGC.
    unsigned long long Xr[REGC ? 2 * QPT : 1];
    unsigned long long Yr[REGC ? 2 * QPT : 1];
    unsigned long long Zr[REGC ? 2 * QPT : 1];
#pragma unroll
    for (int j = 0; j < QPT; j++) {
        const int i0 = 4 * (j * NT + tid);
        float x[4], y[4], z[4];
#pragma unroll
        for (int k = 0; k < 4; k++) {
            const float* g = P + (size_t)(base + i0 + k) * 3;
            x[k] = g[0]; y[k] = g[1]; z[k] = g[2];
            smx[i0 + k] = x[k]; smy[i0 + k] = y[k]; smz[i0 + k] = z[k];
        }
        if (REGC) {
            PACK2(Xr[2 * j], x[0], x[1]); PACK2(Xr[2 * j + 1], x[2], x[3]);
            PACK2(Yr[2 * j], y[0], y[1]); PACK2(Yr[2 * j + 1], y[2], y[3]);
            PACK2(Zr[2 * j], z[0], z[1]); PACK2(Zr[2 * j + 1], z[2], z[3]);
        }
    }
    if (tid < 32) { wv[tid] = 0u; wi[tid] = 0xffffffffu; }
    if (tid < CS) sflag[tid] = 0u;
    if (tid == 0) *rflag = 0u;

    float4 md[QPT];
#pragma unroll
    for (int j = 0; j < QPT; j++) md[j] = make_float4(BIGF, BIGF, BIGF, BIGF);

    __syncthreads();
    cluster_barrier();   // publish smem coords + zeroed flags cluster-wide

    float lx = P[0], ly = P[1], lz = P[2];   // reference: last_idx init = 0

    // Hoisted DSMEM addresses.
    const uint32_t slots_u32 = smem_u32(slots);
    const uint32_t sflag_u32 = smem_u32(sflag);
    const uint32_t res_u32   = smem_u32(res);
    const uint32_t rflag_u32 = smem_u32(rflag);
    // Spoke -> hub (CTA0): this CTA's slot/flag in CTA0's smem.
    const uint32_t hub_slot = mapa_rank(slots_u32 + rank * 32u, 0u);
    const uint32_t hub_flag = mapa_rank(sflag_u32 + rank * 4u, 0u);
    // Hub -> spokes: result/flag in CTA 'lane''s smem (used by warp0 lanes<CS).
    const uint32_t tgt = (uint32_t)(lane < CS ? lane : 0);
    const uint32_t sp_res  = mapa_rank(res_u32, tgt);
    const uint32_t sp_flag = mapa_rank(rflag_u32, tgt);

    for (int s = 0; s < NSAMP; s++) {
        const unsigned stp = (unsigned)(s + 1);

        // Reference scan emits last_idx BEFORE the update.
        if (rank == 0 && tid == 0) {
            float* o = out + ((size_t)b * NSAMP + s) * 3;
            o[0] = lx; o[1] = ly; o[2] = lz;
        }

        unsigned long long NX, NY, NZ;
        {
            float nx = -lx, ny = -ly, nz = -lz;  // x + (-l) == x - l bit-exact
            PACK2(NX, nx, nx); PACK2(NY, ny, ny); PACK2(NZ, nz, nz);
        }

        // ---- distance update (packed f32x2; mul-then-add order = reference) ----
#pragma unroll
        for (int j = 0; j < QPT; j++) {
            unsigned long long xa, xb, ya, yb, za, zb;
            if (REGC) {
                xa = Xr[2 * j]; xb = Xr[2 * j + 1];
                ya = Yr[2 * j]; yb = Yr[2 * j + 1];
                za = Zr[2 * j]; zb = Zr[2 * j + 1];
            } else {
                const int q4 = j * NT + tid;
                float4 X = ((const float4*)smx)[q4];
                float4 Y = ((const float4*)smy)[q4];
                float4 Z = ((const float4*)smz)[q4];
                PACK2(xa, X.x, X.y); PACK2(xb, X.z, X.w);
                PACK2(ya, Y.x, Y.y); PACK2(yb, Y.z, Y.w);
                PACK2(za, Z.x, Z.y); PACK2(zb, Z.z, Z.w);
            }
            unsigned long long sa, sb;
            ADD2(xa, xa, NX); MUL2(xa, xa, xa);
            ADD2(ya, ya, NY); MUL2(ya, ya, ya);
            ADD2(za, za, NZ); MUL2(za, za, za);
            ADD2(sa, xa, ya);
            ADD2(sa, sa, za);
            ADD2(xb, xb, NX); MUL2(xb, xb, xb);
            ADD2(yb, yb, NY); MUL2(yb, yb, yb);
            ADD2(zb, zb, NZ); MUL2(zb, zb, zb);
            ADD2(sb, xb, yb);
            ADD2(sb, sb, zb);
            float d0, d1, d2, d3;
            UNPACK2(d0, d1, sa);
            UNPACK2(d2, d3, sb);
            md[j].x = fminf(md[j].x, d0);
            md[j].y = fminf(md[j].y, d1);
            md[j].z = fminf(md[j].z, d2);
            md[j].w = fminf(md[j].w, d3);
        }

        // ---- thread-local argmax (lowest index wins on ties) ----
        float bestv = md[0].x;
#pragma unroll
        for (int j = 0; j < QPT; j++) {
            bestv = fmaxf(fmaxf(bestv, fmaxf(md[j].x, md[j].y)),
                          fmaxf(md[j].z, md[j].w));
        }
        int besti = 0;
#pragma unroll
        for (int j = QPT - 1; j >= 0; j--) {
            const int ib = 4 * (j * NT + tid);
            if (md[j].w == bestv) besti = ib + 3;
            if (md[j].z == bestv) besti = ib + 2;
            if (md[j].y == bestv) besti = ib + 1;
            if (md[j].x == bestv) besti = ib + 0;
        }

        // ---- warp reduce (REDUX max bits / min idx among holders) ----
        unsigned vb   = __float_as_uint(bestv);
        unsigned wmax = __reduce_max_sync(0xffffffffu, vb);
        unsigned imin = __reduce_min_sync(0xffffffffu,
                                          vb == wmax ? (unsigned)besti : 0xffffffffu);
        if (lane == 0) { wv[warp] = wmax; wi[warp] = imin; }
        __syncthreads();

        if (warp == 0) {
            // ---- CTA reduce ----
            unsigned v2   = wv[lane];
            unsigned i2   = wi[lane];
            unsigned cmax = __reduce_max_sync(0xffffffffu, v2);
            unsigned csel = __reduce_min_sync(0xffffffffu,
                                              v2 == cmax ? i2 : 0xffffffffu);
            // ---- spoke: one lane ships candidate to the hub ----
            if (lane == (int)rank) {
                float cx = smx[csel], cy = smy[csel], cz = smz[csel];
                unsigned gi = (unsigned)(base + (int)csel);
                st_cluster_b64(hub_slot,
                               (unsigned long long)cmax | ((unsigned long long)gi << 32));
                st_cluster_b64(hub_slot + 8, f2_to_u64(cx, cy));
                st_cluster_b32(hub_slot + 16, __float_as_uint(cz));
                st_rel_cluster_b32(hub_flag, stp);
            }
            // ---- hub: collect, reduce, broadcast ----
            if (rank == 0) {
                unsigned f;
                do {
                    f = (lane < CS) ? ld_acq_cluster(sflag_u32 + 4u * lane) : stp;
                } while (__any_sync(0xffffffffu, f < stp));

                unsigned gv = 0u, ggi = 0xffffffffu;
                float gx = 0.f, gy = 0.f, gz = 0.f;
                if (lane < CS) {
                    const float* sl = slots + lane * 8;
                    gv  = ((const unsigned*)sl)[0];
                    ggi = ((const unsigned*)sl)[1];
                    gx  = sl[2];
                    gy  = sl[3];
                    gz  = sl[4];
                }
                unsigned gmax = __reduce_max_sync(0xffffffffu, gv);
                unsigned gsel = __reduce_min_sync(
                    0xffffffffu, (lane < CS && gv == gmax) ? ggi : 0xffffffffu);
                const int wl = (int)(gsel >> LOGPPC);
                gx = __shfl_sync(0xffffffffu, gx, wl);
                gy = __shfl_sync(0xffffffffu, gy, wl);
                gz = __shfl_sync(0xffffffffu, gz, wl);
                if (lane < CS) {
                    st_cluster_b64(sp_res, f2_to_u64(gx, gy));
                    st_cluster_b32(sp_res + 8, __float_as_uint(gz));
                    st_rel_cluster_b32(sp_flag, stp);
                }
            }
        }

        // ---- all threads: wait for the winner, read it (broadcast LDS) ----
        while (ld_acq_cluster(rflag_u32) < stp) {}
        lx = res[0]; ly = res[1]; lz = res[2];
    }
}

__global__ void __cluster_dims__(16, 1, 1) __launch_bounds__(NT, 1)
fps16(const float* __restrict__ pts, float* __restrict__ out) {
    fps_body<16, true>(pts, out);
}
__global__ void __cluster_dims__(8, 1, 1) __launch_bounds__(NT, 1)
fps8(const float* __restrict__ pts, float* __restrict__ out) {
    fps_body<8, false>(pts, out);
}

static size_t smem_bytes(int cs) {
    int ppc = NPTS / cs;
    return (size_t)(3 * ppc + 64 + cs * 8 + cs + 8) * sizeof(float);
}

extern "C" void kernel_launch(void* const* d_in, const int* in_sizes, int n_in,
                              void* d_out, int out_size)
{
    (void)in_sizes; (void)n_in; (void)out_size;
    const float* pts = (const float*)d_in[0];   // point_coord (8, 131072, 3)
    float* out = (float*)d_out;                 // (8, 4096, 3)

    const size_t s16 = smem_bytes(16);
    const size_t s8  = smem_bytes(8);

    cudaFuncSetAttribute(fps16, cudaFuncAttributeNonPortableClusterSizeAllowed, 1);
    cudaFuncSetAttribute(fps16, cudaFuncAttributeMaxDynamicSharedMemorySize, (int)s16);
    cudaFuncSetAttribute(fps8,  cudaFuncAttributeMaxDynamicSharedMemorySize, (int)s8);
    cudaGetLastError();

    int nc = 0;
    cudaLaunchConfig_t cfg = {};
    cfg.gridDim  = dim3(BATCH * 16, 1, 1);
    cfg.blockDim = dim3(NT, 1, 1);
    cfg.dynamicSmemBytes = s16;
    cudaLaunchAttribute at[1];
    at[0].id = cudaLaunchAttributeClusterDimension;
    at[0].val.clusterDim.x = 16;
    at[0].val.clusterDim.y = 1;
    at[0].val.clusterDim.z = 1;
    cfg.attrs = at;
    cfg.numAttrs = 1;
    cudaError_t e = cudaOccupancyMaxActiveClusters(&nc, fps16, &cfg);

    if (e == cudaSuccess && nc > 0) {
        fps16<<<BATCH * 16, NT, s16>>>(pts, out);
    } else {
        cudaGetLastError();
        fps8<<<BATCH * 8, NT, s8>>>(pts, out);
    }
}

// round 6
// speedup vs baseline: 1.3401x; 1.3401x over previous
#include <cuda_runtime.h>
#include <cstdint>

// FPS on GB300, round 5.
// CS=16 clusters, 512 thr/CTA, coords register-resident (R3 base).
// Sync redesign: per-step cluster exchange uses an mbarrier where ONLY warp0
// waits (HW-sleep try_wait); warps 1-15 park at a named bar.sync until warp0
// publishes the winner locally. No barrier.cluster in the loop, no all-thread
// spin (R2/R4's proven failure mode).
//   warp0: CTA REDUX -> lanes<CS all-to-all st.cluster candidate into
//          slot[parity][rank] of every CTA + mbarrier.arrive.release.cluster
//          -> try_wait(parity) -> 16-cand REDUX -> winner xyz to smem
//   all  : bar.sync 1; read winner (broadcast LDS).
// WAR on parity-buffered slots is closed by: read_p(s) < arrive(s+1) <
// wait(s+1) < write_p(s+2).

#define NPTS     131072
#define BATCH    8
#define NSAMP    4096
#define NT       512
#define BIGF     1e10f

#define ADD2(o, a, b) asm("add.rn.f32x2 %0, %1, %2;" : "=l"(o) : "l"(a), "l"(b))
#define MUL2(o, a, b) asm("mul.rn.f32x2 %0, %1, %2;" : "=l"(o) : "l"(a), "l"(b))
#define PACK2(o, lo, hi) asm("mov.b64 %0, {%1, %2};" : "=l"(o) : "f"(lo), "f"(hi))
#define UNPACK2(lo, hi, in) asm("mov.b64 {%0, %1}, %2;" : "=f"(lo), "=f"(hi) : "l"(in))

static __device__ __forceinline__ uint32_t smem_u32(const void* p) {
    uint32_t a;
    asm("{ .reg .u64 t; cvta.to.shared.u64 t, %1; cvt.u32.u64 %0, t; }"
        : "=r"(a) : "l"(p));
    return a;
}
static __device__ __forceinline__ uint32_t mapa_rank(uint32_t local, uint32_t rank) {
    uint32_t r;
    asm("mapa.shared::cluster.u32 %0, %1, %2;" : "=r"(r) : "r"(local), "r"(rank));
    return r;
}
static __device__ __forceinline__ void st_cluster_b64(uint32_t addr, unsigned long long v) {
    asm volatile("st.shared::cluster.b64 [%0], %1;" :: "r"(addr), "l"(v) : "memory");
}
static __device__ __forceinline__ void st_cluster_b32(uint32_t addr, uint32_t v) {
    asm volatile("st.shared::cluster.b32 [%0], %1;" :: "r"(addr), "r"(v) : "memory");
}
static __device__ __forceinline__ void mbar_arrive_remote_release(uint32_t remote_mbar) {
    asm volatile("mbarrier.arrive.release.cluster.shared::cluster.b64 _, [%0];"
                 :: "r"(remote_mbar) : "memory");
}
// Single-warp HW-sleep wait on phase parity (acquire, cluster scope).
static __device__ __forceinline__ void mbar_wait_parity(uint32_t mbar, uint32_t parity) {
    asm volatile(
        "{\n\t"
        ".reg .pred P;\n\t"
        "WL_%=:\n\t"
        "mbarrier.try_wait.parity.acquire.cluster.shared::cta.b64 P, [%0], %1, 0x989680;\n\t"
        "@!P bra WL_%=;\n\t"
        "}" :: "r"(mbar), "r"(parity) : "memory");
}
static __device__ __forceinline__ unsigned long long f2_to_u64(float a, float b) {
    unsigned long long r;
    asm("mov.b64 %0, {%1, %2};" : "=l"(r) : "f"(a), "f"(b));
    return r;
}
static __device__ __forceinline__ void cluster_barrier() {
    asm volatile("barrier.cluster.arrive.aligned;" ::: "memory");
    asm volatile("barrier.cluster.wait.aligned;" ::: "memory");
}
static __device__ __forceinline__ void named_bar(int id, int count) {
    asm volatile("bar.sync %0, %1;" :: "r"(id), "r"(count) : "memory");
}

template <int CS, bool REGC>
__device__ __forceinline__ void fps_body(const float* __restrict__ pts,
                                         float* __restrict__ out)
{
    constexpr int PPC    = NPTS / CS;
    constexpr int QPT    = PPC / (4 * NT);
    constexpr int LOGPPC = (CS == 16) ? 13 : 14;

    extern __shared__ float sm[];
    float*    smx   = sm;
    float*    smy   = sm + PPC;
    float*    smz   = sm + 2 * PPC;
    unsigned* wv    = (unsigned*)(sm + 3 * PPC);    // [32] warp best value bits
    unsigned* wi    = wv + 32;                      // [32] warp best local idx
    float*    slots = (float*)(wi + 32);            // [2][CS][8] candidate slots
    float*    res   = slots + 2 * CS * 8;           // [4] winner xyz
    unsigned long long* mbar = (unsigned long long*)(res + 4);

    const int tid  = threadIdx.x;
    const int lane = tid & 31;
    const int warp = tid >> 5;
    uint32_t rank;
    asm("mov.u32 %0, %%cluster_ctarank;" : "=r"(rank));
    const int b = blockIdx.x / CS;
    const float* P = pts + (size_t)b * NPTS * 3;
    const int base = (int)rank * PPC;

    // Load coords: SMEM SoA copy (winner lookup) + f32x2 register cache.
    unsigned long long Xr[REGC ? 2 * QPT : 1];
    unsigned long long Yr[REGC ? 2 * QPT : 1];
    unsigned long long Zr[REGC ? 2 * QPT : 1];
#pragma unroll
    for (int j = 0; j < QPT; j++) {
        const int i0 = 4 * (j * NT + tid);
        float x[4], y[4], z[4];
#pragma unroll
        for (int k = 0; k < 4; k++) {
            const float* g = P + (size_t)(base + i0 + k) * 3;
            x[k] = g[0]; y[k] = g[1]; z[k] = g[2];
            smx[i0 + k] = x[k]; smy[i0 + k] = y[k]; smz[i0 + k] = z[k];
        }
        if (REGC) {
            PACK2(Xr[2 * j], x[0], x[1]); PACK2(Xr[2 * j + 1], x[2], x[3]);
            PACK2(Yr[2 * j], y[0], y[1]); PACK2(Yr[2 * j + 1], y[2], y[3]);
            PACK2(Zr[2 * j], z[0], z[1]); PACK2(Zr[2 * j + 1], z[2], z[3]);
        }
    }
    if (tid < 32) { wv[tid] = 0u; wi[tid] = 0xffffffffu; }  // pad lanes 16..31

    const uint32_t mbar_u32 = smem_u32(mbar);
    if (tid == 0) {
        asm volatile("mbarrier.init.shared.b64 [%0], %1;"
                     :: "r"(mbar_u32), "r"((unsigned)CS) : "memory");
    }

    float4 md[QPT];
#pragma unroll
    for (int j = 0; j < QPT; j++) md[j] = make_float4(BIGF, BIGF, BIGF, BIGF);

    __syncthreads();
    cluster_barrier();   // publish smem coords + mbarrier init cluster-wide

    float lx = P[0], ly = P[1], lz = P[2];   // reference: last_idx init = 0

    // Hoisted DSMEM addresses (used by warp0 lanes<CS).
    const uint32_t slots_u32 = smem_u32(slots);
    const uint32_t tgt = (uint32_t)(lane < CS ? lane : 0);
    const uint32_t rslot0 = mapa_rank(slots_u32 + rank * 32u, tgt);
    const uint32_t rslot1 = rslot0 + (uint32_t)(CS * 32);
    const uint32_t rmbar  = mapa_rank(mbar_u32, tgt);

    for (int s = 0; s < NSAMP; s++) {
        const uint32_t p = (uint32_t)(s & 1);

        // Reference scan emits last_idx BEFORE the update.
        if (rank == 0 && tid == 0) {
            float* o = out + ((size_t)b * NSAMP + s) * 3;
            o[0] = lx; o[1] = ly; o[2] = lz;
        }

        unsigned long long NX, NY, NZ;
        {
            float nx = -lx, ny = -ly, nz = -lz;  // x + (-l) == x - l bit-exact
            PACK2(NX, nx, nx); PACK2(NY, ny, ny); PACK2(NZ, nz, nz);
        }

        // ---- distance update (packed f32x2; mul-then-add order = reference) ----
#pragma unroll
        for (int j = 0; j < QPT; j++) {
            unsigned long long xa, xb, ya, yb, za, zb;
            if (REGC) {
                xa = Xr[2 * j]; xb = Xr[2 * j + 1];
                ya = Yr[2 * j]; yb = Yr[2 * j + 1];
                za = Zr[2 * j]; zb = Zr[2 * j + 1];
            } else {
                const int q4 = j * NT + tid;
                float4 X = ((const float4*)smx)[q4];
                float4 Y = ((const float4*)smy)[q4];
                float4 Z = ((const float4*)smz)[q4];
                PACK2(xa, X.x, X.y); PACK2(xb, X.z, X.w);
                PACK2(ya, Y.x, Y.y); PACK2(yb, Y.z, Y.w);
                PACK2(za, Z.x, Z.y); PACK2(zb, Z.z, Z.w);
            }
            unsigned long long sa, sb;
            ADD2(xa, xa, NX); MUL2(xa, xa, xa);
            ADD2(ya, ya, NY); MUL2(ya, ya, ya);
            ADD2(za, za, NZ); MUL2(za, za, za);
            ADD2(sa, xa, ya);
            ADD2(sa, sa, za);
            ADD2(xb, xb, NX); MUL2(xb, xb, xb);
            ADD2(yb, yb, NY); MUL2(yb, yb, yb);
            ADD2(zb, zb, NZ); MUL2(zb, zb, zb);
            ADD2(sb, xb, yb);
            ADD2(sb, sb, zb);
            float d0, d1, d2, d3;
            UNPACK2(d0, d1, sa);
            UNPACK2(d2, d3, sb);
            md[j].x = fminf(md[j].x, d0);
            md[j].y = fminf(md[j].y, d1);
            md[j].z = fminf(md[j].z, d2);
            md[j].w = fminf(md[j].w, d3);
        }

        // ---- thread-local argmax (lowest index wins on ties) ----
        float bestv = md[0].x;
#pragma unroll
        for (int j = 0; j < QPT; j++) {
            bestv = fmaxf(fmaxf(bestv, fmaxf(md[j].x, md[j].y)),
                          fmaxf(md[j].z, md[j].w));
        }
        int besti = 0;
#pragma unroll
        for (int j = QPT - 1; j >= 0; j--) {
            const int ib = 4 * (j * NT + tid);
            if (md[j].w == bestv) besti = ib + 3;
            if (md[j].z == bestv) besti = ib + 2;
            if (md[j].y == bestv) besti = ib + 1;
            if (md[j].x == bestv) besti = ib + 0;
        }

        // ---- warp reduce (REDUX max bits / min idx among holders) ----
        unsigned vb   = __float_as_uint(bestv);
        unsigned wmax = __reduce_max_sync(0xffffffffu, vb);
        unsigned imin = __reduce_min_sync(0xffffffffu,
                                          vb == wmax ? (unsigned)besti : 0xffffffffu);
        if (lane == 0) { wv[warp] = wmax; wi[warp] = imin; }
        named_bar(0, NT);   // publish wv/wi to warp0

        if (warp == 0) {
            // ---- CTA reduce ----
            unsigned v2   = wv[lane];
            unsigned i2   = wi[lane];
            unsigned cmax = __reduce_max_sync(0xffffffffu, v2);
            unsigned csel = __reduce_min_sync(0xffffffffu,
                                              v2 == cmax ? i2 : 0xffffffffu);
            // ---- all-to-all publish + remote arrive (release) ----
            if (lane < CS) {
                float cx = smx[csel], cy = smy[csel], cz = smz[csel];
                unsigned gi = (unsigned)(base + (int)csel);
                uint32_t dst = p ? rslot1 : rslot0;
                st_cluster_b64(dst,
                               (unsigned long long)cmax | ((unsigned long long)gi << 32));
                st_cluster_b64(dst + 8, f2_to_u64(cx, cy));
                st_cluster_b32(dst + 16, __float_as_uint(cz));
                mbar_arrive_remote_release(rmbar);
            }
            // ---- single-warp wait for all CS arrivals ----
            mbar_wait_parity(mbar_u32, p);

            // ---- cluster reduce over CS candidates ----
            const float* slot = slots + (p * CS + (unsigned)lane) * 8;
            unsigned gv = 0u, ggi = 0xffffffffu;
            float gx = 0.f, gy = 0.f, gz = 0.f;
            if (lane < CS) {
                gv  = ((const unsigned*)slot)[0];
                ggi = ((const unsigned*)slot)[1];
                gx  = slot[2];
                gy  = slot[3];
                gz  = slot[4];
            }
            unsigned gmax = __reduce_max_sync(0xffffffffu, gv);
            unsigned gsel = __reduce_min_sync(
                0xffffffffu, (lane < CS && gv == gmax) ? ggi : 0xffffffffu);
            const int wl = (int)(gsel >> LOGPPC);
            gx = __shfl_sync(0xffffffffu, gx, wl);
            gy = __shfl_sync(0xffffffffu, gy, wl);
            gz = __shfl_sync(0xffffffffu, gz, wl);
            if (lane == 0) { res[0] = gx; res[1] = gy; res[2] = gz; }
        }

        // ---- release all warps; read winner (broadcast LDS) ----
        named_bar(1, NT);
        lx = res[0]; ly = res[1]; lz = res[2];
    }
}

__global__ void __cluster_dims__(16, 1, 1) __launch_bounds__(NT, 1)
fps16(const float* __restrict__ pts, float* __restrict__ out) {
    fps_body<16, true>(pts, out);
}
__global__ void __cluster_dims__(8, 1, 1) __launch_bounds__(NT, 1)
fps8(const float* __restrict__ pts, float* __restrict__ out) {
    fps_body<8, false>(pts, out);
}

static size_t smem_bytes(int cs) {
    int ppc = NPTS / cs;
    return (size_t)(3 * ppc + 64 + 2 * cs * 8 + 4 + 4) * sizeof(float);
}

extern "C" void kernel_launch(void* const* d_in, const int* in_sizes, int n_in,
                              void* d_out, int out_size)
{
    (void)in_sizes; (void)n_in; (void)out_size;
    const float* pts = (const float*)d_in[0];   // point_coord (8, 131072, 3)
    float* out = (float*)d_out;                 // (8, 4096, 3)

    const size_t s16 = smem_bytes(16);
    const size_t s8  = smem_bytes(8);

    cudaFuncSetAttribute(fps16, cudaFuncAttributeNonPortableClusterSizeAllowed, 1);
    cudaFuncSetAttribute(fps16, cudaFuncAttributeMaxDynamicSharedMemorySize, (int)s16);
    cudaFuncSetAttribute(fps8,  cudaFuncAttributeMaxDynamicSharedMemorySize, (int)s8);
    cudaGetLastError();

    int nc = 0;
    cudaLaunchConfig_t cfg = {};
    cfg.gridDim  = dim3(BATCH * 16, 1, 1);
    cfg.blockDim = dim3(NT, 1, 1);
    cfg.dynamicSmemBytes = s16;
    cudaLaunchAttribute at[1];
    at[0].id = cudaLaunchAttributeClusterDimension;
    at[0].val.clusterDim.x = 16;
    at[0].val.clusterDim.y = 1;
    at[0].val.clusterDim.z = 1;
    cfg.attrs = at;
    cfg.numAttrs = 1;
    cudaError_t e = cudaOccupancyMaxActiveClusters(&nc, fps16, &cfg);

    if (e == cudaSuccess && nc > 0) {
        fps16<<<BATCH * 16, NT, s16>>>(pts, out);
    } else {
        cudaGetLastError();
        fps8<<<BATCH * 8, NT, s8>>>(pts, out);
    }
}